// round 1
// baseline (speedup 1.0000x reference)
#include <cuda_runtime.h>
#include <cuda_bf16.h>
#include <stdint.h>

#define BB 8
#define AA 26880
#define KK 2048
#define CAP 4096        // valid-candidate capacity per batch (Nv ~ 1344, 75 sigma margin)
#define PCAP 4096       // conflict-pair capacity per batch (expected ~10)
#define TILE 64

// ---------------- device scratch (no allocations allowed) ----------------
__device__ unsigned            g_cnt[BB];
__device__ unsigned long long  g_valid[BB][CAP];
__device__ float               g_topscore[BB][KK];
__device__ int                 g_topidx[BB][KK];
__device__ int                 g_nv[BB];
__device__ float4              g_boxes[BB][KK];
__device__ unsigned            g_paircnt[BB];
__device__ unsigned            g_pairs[BB][PCAP];

// ---------------- K0: zero counters ----------------
__global__ void k_zero() {
    int t = threadIdx.x;
    if (t < BB) { g_cnt[t] = 0u; g_paircnt[t] = 0u; }
}

// ---------------- K1: compact valid (score >= 0.1) candidates ----------------
// key = (score_bits << 32) | (0xFFFFFFFF - idx): descending sort gives
// score desc, idx asc on ties (scores are all positive floats -> bit pattern is order-preserving)
__global__ void k_compact(const float* __restrict__ preds) {
    int b = blockIdx.y;
    int a = blockIdx.x * blockDim.x + threadIdx.x;
    if (a >= AA) return;
    float s = preds[(size_t)b * 5 * AA + (size_t)4 * AA + a];
    if (s >= 0.1f) {
        unsigned pos = atomicAdd(&g_cnt[b], 1u);
        if (pos < CAP) {
            g_valid[b][pos] =
                ((unsigned long long)__float_as_uint(s) << 32) |
                (unsigned long long)(0xFFFFFFFFu - (unsigned)a);
        }
    }
}

// ---------------- K2: per-batch bitonic sort (desc) + tail fill ----------------
__global__ void __launch_bounds__(1024) k_sort(const float* __restrict__ preds) {
    int b = blockIdx.x;
    int t = threadIdx.x;           // 1024 threads
    __shared__ unsigned long long sk[CAP];   // 32 KB
    __shared__ int ssc[1024];
    __shared__ int s_written;

    unsigned cnt = g_cnt[b];
    if (cnt > CAP) cnt = CAP;

    for (int e = t; e < CAP; e += 1024)
        sk[e] = (e < (int)cnt) ? g_valid[b][e] : 0ULL;
    __syncthreads();

    // bitonic sort, descending
    for (int size = 2; size <= CAP; size <<= 1) {
        for (int stride = size >> 1; stride > 0; stride >>= 1) {
            for (int e = t; e < CAP; e += 1024) {
                int p = e ^ stride;
                if (p > e) {
                    bool descSeg = ((e & size) == 0);
                    unsigned long long a0 = sk[e], a1 = sk[p];
                    bool sw = descSeg ? (a0 < a1) : (a0 > a1);
                    if (sw) { sk[e] = a1; sk[p] = a0; }
                }
            }
            __syncthreads();
        }
    }

    int Nvc = ((int)cnt < KK) ? (int)cnt : KK;
    if (t == 0) g_nv[b] = Nvc;

    for (int k = t; k < Nvc; k += 1024) {
        unsigned long long key = sk[k];
        g_topscore[b][k] = __uint_as_float((unsigned)(key >> 32));
        g_topidx[b][k]   = (int)(0xFFFFFFFFu - (unsigned)(key & 0xFFFFFFFFu));
    }

    // tail: first (K - Nvc) invalid anchors in ascending index order, value -1.0
    int needed = KK - Nvc;
    if (needed > 0) {
        if (t == 0) s_written = 0;
        __syncthreads();
        const float* sc = preds + (size_t)b * 5 * AA + (size_t)4 * AA;
        for (int start = 0; start < AA; start += 1024) {
            int a = start + t;
            int flag = (a < AA && sc[a] < 0.1f) ? 1 : 0;
            ssc[t] = flag;
            __syncthreads();
            for (int off = 1; off < 1024; off <<= 1) {
                int v = (t >= off) ? ssc[t - off] : 0;
                __syncthreads();
                ssc[t] += v;
                __syncthreads();
            }
            int incl = ssc[t];
            int excl = incl - flag;
            int total = ssc[1023];
            int w0 = s_written;
            if (flag && (w0 + excl) < needed) {
                int slot = Nvc + w0 + excl;
                g_topscore[b][slot] = -1.0f;
                g_topidx[b][slot]   = a;
            }
            __syncthreads();
            if (t == 0) s_written = w0 + total;
            __syncthreads();
            if (w0 + total >= needed) break;
        }
    }
}

// ---------------- K3: gather boxes, write dets + initial keep ----------------
__global__ void k_gather(const float* __restrict__ preds, float* __restrict__ out) {
    int g = blockIdx.x * blockDim.x + threadIdx.x;
    if (g >= BB * KK) return;
    int b = g / KK, k = g % KK;
    int idx = g_topidx[b][k];
    const float* base = preds + (size_t)b * 5 * AA;
    float cx = base[idx];
    float cy = base[AA + idx];
    float w  = base[2 * AA + idx];
    float h  = base[3 * AA + idx];
    float hw = w * 0.5f, hh = h * 0.5f;
    float bx1 = cx - hw, by1 = cy - hh, bx2 = cx + hw, by2 = cy + hh;
    g_boxes[b][k] = make_float4(bx1, by1, bx2, by2);

    // scale = DET_SCALE / IMG_SIZE = [1.5, 1.0546875, 1.5, 1.0546875] (exact fp32)
    float s1 = bx1 * 1.5f + 1.0f;
    float s2 = by1 * 1.0546875f + 1.0f;
    float s3 = bx2 * 1.5f + 1.0f;
    float s4 = by2 * 1.0546875f + 1.0f;

    float* d = out + (size_t)g * 5;
    d[0] = (s1 + s3) * 0.5f;
    d[1] = (s2 + s4) * 0.5f;
    d[2] = s3 - s1;
    d[3] = s4 - s2;
    d[4] = g_topscore[b][k];

    out[(size_t)BB * KK * 5 + g] = (k < g_nv[b]) ? 1.0f : 0.0f;
}

// ---------------- K4: sparse conflict pairs (IoU > 0.7, i < j, both valid) ----------------
__global__ void __launch_bounds__(256) k_pairs() {
    int b = blockIdx.z;
    int Nv = g_nv[b];
    int i0 = blockIdx.y * TILE;
    int j0 = blockIdx.x * TILE;
    if (blockIdx.y > blockIdx.x) return;       // tile entirely below diagonal
    if (i0 >= Nv || j0 >= Nv) return;

    __shared__ float4 sbi[TILE];
    __shared__ float4 sbj[TILE];
    int t = threadIdx.x; // 256
    if (t < TILE) {
        sbi[t] = (i0 + t < Nv) ? g_boxes[b][i0 + t] : make_float4(0.f, 0.f, 0.f, 0.f);
    } else if (t < 2 * TILE) {
        int u = t - TILE;
        sbj[u] = (j0 + u < Nv) ? g_boxes[b][j0 + u] : make_float4(0.f, 0.f, 0.f, 0.f);
    }
    __syncthreads();

    int jl = t & 63;
    int j = j0 + jl;
    if (j >= Nv) return;
    float4 bj = sbj[jl];
    float aj = (bj.z - bj.x) * (bj.w - bj.y);

    #pragma unroll 4
    for (int ii = (t >> 6); ii < TILE; ii += 4) {
        int i = i0 + ii;
        if (i >= Nv || i >= j) continue;
        float4 bi = sbi[ii];
        float ai = (bi.z - bi.x) * (bi.w - bi.y);
        float lx = fmaxf(bi.x, bj.x), ly = fmaxf(bi.y, bj.y);
        float rx = fminf(bi.z, bj.z), ry = fminf(bi.w, bj.w);
        float iw = fmaxf(rx - lx, 0.f), ih = fmaxf(ry - ly, 0.f);
        float inter = iw * ih;
        float iou = inter / (ai + aj - inter);
        if (iou > 0.7f) {
            unsigned pos = atomicAdd(&g_paircnt[b], 1u);
            if (pos < PCAP)
                g_pairs[b][pos] = ((unsigned)j << 16) | (unsigned)i;   // sortable by target j
        }
    }
}

// ---------------- K5: exact greedy resolution over the (tiny) conflict list ----------------
__global__ void k_resolve(float* __restrict__ out) {
    int b = blockIdx.x;
    int t = threadIdx.x; // 32
    __shared__ unsigned sp[PCAP];        // 16 KB
    __shared__ unsigned char skeep[KK];  // 2 KB
    int Nv = g_nv[b];
    unsigned n = g_paircnt[b];
    if (n > PCAP) n = PCAP;

    for (int k = t; k < KK; k += 32) skeep[k] = (k < Nv) ? 1 : 0;
    for (unsigned p = t; p < n; p += 32) sp[p] = g_pairs[b][p];
    __syncthreads();

    if (t == 0) {
        // sort ascending by packed (j<<16 | i) -> by suppression target j
        for (unsigned x = 1; x < n; x++) {
            unsigned v = sp[x];
            int y = (int)x - 1;
            while (y >= 0 && sp[y] > v) { sp[y + 1] = sp[y]; y--; }
            sp[y + 1] = v;
        }
        // greedy: process targets in ascending sorted position; keep[i] for i<j is final
        for (unsigned x = 0; x < n; x++) {
            unsigned v = sp[x];
            int j = (int)(v >> 16), i = (int)(v & 0xFFFFu);
            if (skeep[i] && skeep[j]) {
                skeep[j] = 0;
                out[(size_t)BB * KK * 5 + (size_t)b * KK + j] = 0.0f;
            }
        }
    }
}

// ---------------- launch ----------------
extern "C" void kernel_launch(void* const* d_in, const int* in_sizes, int n_in,
                              void* d_out, int out_size) {
    const float* preds = (const float*)d_in[0];
    float* out = (float*)d_out;
    (void)in_sizes; (void)n_in; (void)out_size;

    k_zero<<<1, 32>>>();
    k_compact<<<dim3((AA + 255) / 256, BB), 256>>>(preds);
    k_sort<<<BB, 1024>>>(preds);
    k_gather<<<(BB * KK + 255) / 256, 256>>>(preds, out);
    k_pairs<<<dim3(KK / TILE, KK / TILE, BB), 256>>>();
    k_resolve<<<BB, 32>>>(out);
}

// round 2
// speedup vs baseline: 2.1031x; 2.1031x over previous
#include <cuda_runtime.h>
#include <cuda_bf16.h>
#include <stdint.h>

#define BB 8
#define AA 26880
#define KK 2048
#define CAP 4096        // valid-candidate capacity per batch (Nv ~ 1344)
#define PCAP 2048       // conflict-pair capacity per batch (expected ~10)
#define NCH 105         // 26880 / 256 anchor chunks per batch
#define TILE 64

// ---------------- device scratch ----------------
__device__ unsigned            g_cnt[BB];
__device__ unsigned long long  g_valid[BB][CAP];
__device__ int                 g_nv[BB];
__device__ float4              g_boxes[BB][KK];
__device__ unsigned            g_paircnt[BB];
__device__ unsigned            g_pairs[BB][PCAP];
__device__ unsigned            g_invcnt[BB][NCH];

// ---------------- K0: zero counters ----------------
__global__ void k_zero() {
    int t = threadIdx.x;
    if (t < BB) { g_cnt[t] = 0u; g_paircnt[t] = 0u; }
    if (t < BB * NCH) ((unsigned*)g_invcnt)[t] = 0u;
}

// ---------------- K1: compact valid candidates + per-chunk invalid counts ----------------
// key = (score_bits << 32) | (0xFFFFFFFF - idx): rank by descending key gives
// score desc, idx asc on ties (scores positive -> bit pattern order-preserving)
__global__ void __launch_bounds__(256) k_compact(const float* __restrict__ preds) {
    int b = blockIdx.y;
    int blk = blockIdx.x;               // 105 chunks of 256 (105*256 == 26880 exactly)
    int t = threadIdx.x;
    int a = blk * 256 + t;
    float s = preds[(size_t)b * 5 * AA + (size_t)4 * AA + a];
    bool val = (s >= 0.1f);
    if (val) {
        unsigned pos = atomicAdd(&g_cnt[b], 1u);
        if (pos < CAP) {
            g_valid[b][pos] =
                ((unsigned long long)__float_as_uint(s) << 32) |
                (unsigned long long)(0xFFFFFFFFu - (unsigned)a);
        }
    }
    unsigned bal = __ballot_sync(0xFFFFFFFFu, !val);
    if ((t & 31) == 0) atomicAdd(&g_invcnt[b][blk], (unsigned)__popc(bal));
}

// ---------------- K2: rank sort (warp per candidate) + fused gather for valid slots ----------------
__global__ void __launch_bounds__(256) k_rank(const float* __restrict__ preds,
                                              float* __restrict__ out) {
    int b = blockIdx.y;
    int w = blockIdx.x * 8 + (threadIdx.x >> 5);   // global warp id in [0,256)
    int lane = threadIdx.x & 31;

    unsigned cnt = g_cnt[b];
    if (cnt > CAP) cnt = CAP;
    int Nv = ((int)cnt < KK) ? (int)cnt : KK;
    if (blockIdx.x == 0 && threadIdx.x == 0) g_nv[b] = Nv;

    const unsigned long long* keys = g_valid[b];
    const float* base = preds + (size_t)b * 5 * AA;

    for (int c = w; c < (int)cnt; c += 256) {
        unsigned long long mykey = __ldg(&keys[c]);
        int r = 0;
        for (int m = lane; m < (int)cnt; m += 32)
            r += (__ldg(&keys[m]) > mykey) ? 1 : 0;
        #pragma unroll
        for (int off = 16; off; off >>= 1)
            r += __shfl_xor_sync(0xFFFFFFFFu, r, off);

        if (r < KK) {  // r is warp-uniform after reduction
            int idx = (int)(0xFFFFFFFFu - (unsigned)(mykey & 0xFFFFFFFFu));
            float score = __uint_as_float((unsigned)(mykey >> 32));
            float v = 0.f;
            if (lane < 4) v = __ldg(&base[(size_t)lane * AA + idx]);
            float cx = __shfl_sync(0xFFFFFFFFu, v, 0);
            float cy = __shfl_sync(0xFFFFFFFFu, v, 1);
            float ww = __shfl_sync(0xFFFFFFFFu, v, 2);
            float hh = __shfl_sync(0xFFFFFFFFu, v, 3);
            if (lane == 0) {
                float hw = ww * 0.5f, hv = hh * 0.5f;
                float x1 = cx - hw, y1 = cy - hv, x2 = cx + hw, y2 = cy + hv;
                g_boxes[b][r] = make_float4(x1, y1, x2, y2);
                float s1 = x1 * 1.5f + 1.0f;
                float s2 = y1 * 1.0546875f + 1.0f;
                float s3 = x2 * 1.5f + 1.0f;
                float s4 = y2 * 1.0546875f + 1.0f;
                float* d = out + ((size_t)b * KK + r) * 5;
                d[0] = (s1 + s3) * 0.5f;
                d[1] = (s2 + s4) * 0.5f;
                d[2] = s3 - s1;
                d[3] = s4 - s2;
                d[4] = score;
                out[(size_t)BB * KK * 5 + (size_t)b * KK + r] = 1.0f;
            }
        }
    }
}

// ---------------- K3: tail fill (first K-Nv invalid anchors, asc index) + fused gather ----------------
__global__ void __launch_bounds__(256) k_tail(const float* __restrict__ preds,
                                              float* __restrict__ out) {
    int b = blockIdx.y, c = blockIdx.x, t = threadIdx.x;
    __shared__ unsigned spre[256];
    __shared__ unsigned swsum[8];

    int Nv = g_nv[b];
    int needed = KK - Nv;
    if (needed <= 0) return;

    // prefix = total invalid anchors in chunks [0, c)
    spre[t] = (t < c) ? g_invcnt[b][t] : 0u;   // c <= 104 < 256
    __syncthreads();
    #pragma unroll
    for (int off = 128; off; off >>= 1) {
        if (t < off) spre[t] += spre[t + off];
        __syncthreads();
    }
    int prefix = (int)spre[0];
    if (prefix >= needed) return;   // uniform exit

    int a = c * 256 + t;
    float s = preds[(size_t)b * 5 * AA + (size_t)4 * AA + a];
    bool inv = (s < 0.1f);
    unsigned bal = __ballot_sync(0xFFFFFFFFu, inv);
    int wid = t >> 5, lane = t & 31;
    if (lane == 0) swsum[wid] = (unsigned)__popc(bal);
    __syncthreads();
    int wbase = 0;
    for (int q = 0; q < wid; q++) wbase += (int)swsum[q];
    int r = prefix + wbase + __popc(bal & ((1u << lane) - 1u));

    if (inv && r < needed) {
        int slot = Nv + r;
        const float* base = preds + (size_t)b * 5 * AA;
        float cx = base[a], cy = base[AA + a];
        float ww = base[2 * AA + a], hh = base[3 * AA + a];
        float hw = ww * 0.5f, hv = hh * 0.5f;
        float x1 = cx - hw, y1 = cy - hv, x2 = cx + hw, y2 = cy + hv;
        float s1 = x1 * 1.5f + 1.0f;
        float s2 = y1 * 1.0546875f + 1.0f;
        float s3 = x2 * 1.5f + 1.0f;
        float s4 = y2 * 1.0546875f + 1.0f;
        float* d = out + ((size_t)b * KK + slot) * 5;
        d[0] = (s1 + s3) * 0.5f;
        d[1] = (s2 + s4) * 0.5f;
        d[2] = s3 - s1;
        d[3] = s4 - s2;
        d[4] = -1.0f;
        out[(size_t)BB * KK * 5 + (size_t)b * KK + slot] = 0.0f;
    }
}

// ---------------- K4: sparse conflict pairs over linearized upper-triangle tiles ----------------
__global__ void __launch_bounds__(256) k_pairs() {
    int b = blockIdx.y;
    int Nv = g_nv[b];
    int nt = (Nv + TILE - 1) / TILE;
    int T = nt * (nt + 1) / 2;
    int bx = blockIdx.x;
    if (bx >= T) return;

    // map linear bx -> upper-triangle tile (i <= j)
    int i = 0, S = 0;
    while (bx >= S + (nt - i)) { S += nt - i; i++; }
    int j = i + (bx - S);
    int i0 = i * TILE, j0 = j * TILE;

    __shared__ float4 sbi[TILE];
    __shared__ float  sai[TILE];
    __shared__ float4 sbj[TILE];
    __shared__ float  saj[TILE];
    int t = threadIdx.x;
    if (t < TILE) {
        float4 bi = (i0 + t < Nv) ? g_boxes[b][i0 + t] : make_float4(0.f, 0.f, 0.f, 0.f);
        sbi[t] = bi; sai[t] = (bi.z - bi.x) * (bi.w - bi.y);
    } else if (t < 2 * TILE) {
        int u = t - TILE;
        float4 bj = (j0 + u < Nv) ? g_boxes[b][j0 + u] : make_float4(0.f, 0.f, 0.f, 0.f);
        sbj[u] = bj; saj[u] = (bj.z - bj.x) * (bj.w - bj.y);
    }
    __syncthreads();

    int jl = t & 63;
    int jj = j0 + jl;
    if (jj >= Nv) return;
    float4 bj = sbj[jl];
    float aj = saj[jl];

    #pragma unroll
    for (int q = 0; q < 16; q++) {
        int ii = (t >> 6) + q * 4;
        int gi = i0 + ii;
        if (gi >= Nv || gi >= jj) continue;
        float4 bi = sbi[ii];
        float lx = fmaxf(bi.x, bj.x), ly = fmaxf(bi.y, bj.y);
        float rx = fminf(bi.z, bj.z), ry = fminf(bi.w, bj.w);
        float iw = fmaxf(rx - lx, 0.f), ih = fmaxf(ry - ly, 0.f);
        float inter = iw * ih;
        // iou > 0.7  <=>  inter > 0.7 * union   (union > 0)
        if (inter > 0.7f * (sai[ii] + aj - inter)) {
            unsigned pos = atomicAdd(&g_paircnt[b], 1u);
            if (pos < PCAP)
                g_pairs[b][pos] = ((unsigned)jj << 16) | (unsigned)gi;
        }
    }
}

// ---------------- K5: exact greedy resolution over the tiny conflict list ----------------
__global__ void k_resolve(float* __restrict__ out) {
    int b = blockIdx.x;
    int t = threadIdx.x; // 32
    __shared__ unsigned sp[PCAP];        // 8 KB
    __shared__ unsigned char skeep[KK];  // 2 KB
    int Nv = g_nv[b];
    unsigned n = g_paircnt[b];
    if (n > PCAP) n = PCAP;

    for (int k = t; k < KK; k += 32) skeep[k] = (k < Nv) ? 1 : 0;
    for (unsigned p = t; p < n; p += 32) sp[p] = g_pairs[b][p];
    __syncthreads();

    if (t == 0) {
        // sort ascending by packed (j<<16 | i) -> process suppression targets j ascending
        for (unsigned x = 1; x < n; x++) {
            unsigned v = sp[x];
            int y = (int)x - 1;
            while (y >= 0 && sp[y] > v) { sp[y + 1] = sp[y]; y--; }
            sp[y + 1] = v;
        }
        for (unsigned x = 0; x < n; x++) {
            unsigned v = sp[x];
            int j = (int)(v >> 16), i = (int)(v & 0xFFFFu);
            if (skeep[i] && skeep[j]) {
                skeep[j] = 0;
                out[(size_t)BB * KK * 5 + (size_t)b * KK + j] = 0.0f;
            }
        }
    }
}

// ---------------- launch ----------------
extern "C" void kernel_launch(void* const* d_in, const int* in_sizes, int n_in,
                              void* d_out, int out_size) {
    const float* preds = (const float*)d_in[0];
    float* out = (float*)d_out;
    (void)in_sizes; (void)n_in; (void)out_size;

    k_zero   <<<1, 1024>>>();
    k_compact<<<dim3(NCH, BB), 256>>>(preds);
    k_rank   <<<dim3(32, BB), 256>>>(preds, out);
    k_tail   <<<dim3(NCH, BB), 256>>>(preds, out);
    k_pairs  <<<dim3(528, BB), 256>>>();
    k_resolve<<<BB, 32>>>(out);
}